// round 8
// baseline (speedup 1.0000x reference)
#include <cuda_runtime.h>
#include <math.h>

// Problem constants
#define BB   4
#define CIN  128
#define HH   96
#define WWW  96
#define OO   128
#define PP   9216      // H*W
#define PT   64        // pixel tile per block
#define NPT  144       // PP / PT

typedef unsigned long long ull;

// Scratch (device globals — no allocation allowed)
__device__ float g_off [BB * 18 * PP];     // (b, 2k+d, p)
__device__ float g_mask[BB * 9  * PP];     // (b, k, p) — sigmoid applied
__device__ ull   g_wt2 [9 * CIN * OO];     // (k, c, o) deform_w duplicated as f32x2
__device__ ull   g_owt2[9 * CIN * 32];     // (k, c, slot) offset/mask w duplicated

// ---- packed fp32x2 helpers (Blackwell FFMA2) --------------------------------
__device__ __forceinline__ void fma2(ull& d, ull a, ull b) {
    asm("fma.rn.f32x2 %0, %1, %2, %0;" : "+l"(d) : "l"(a), "l"(b));
}
__device__ __forceinline__ float2 unpack2(ull v) {
    unsigned lo, hi;
    asm("mov.b64 {%0, %1}, %2;" : "=r"(lo), "=r"(hi) : "l"(v));
    return make_float2(__uint_as_float(lo), __uint_as_float(hi));
}
__device__ __forceinline__ ull dup_host(float w) {
    unsigned u = __float_as_uint(w);
    return (ull)u | ((ull)u << 32);
}
// ---- cp.async helpers -------------------------------------------------------
__device__ __forceinline__ void cp_async16(void* smem, const void* gmem) {
    unsigned s = (unsigned)__cvta_generic_to_shared(smem);
    asm volatile("cp.async.ca.shared.global [%0], [%1], 16;\n" :: "r"(s), "l"(gmem));
}
__device__ __forceinline__ void cp_commit() {
    asm volatile("cp.async.commit_group;\n");
}
__device__ __forceinline__ void cp_wait0() {
    asm volatile("cp.async.wait_group 0;\n" ::: "memory");
}

// ---------------------------------------------------------------------------
// Kernel 0: one-time weight transpose + f32x2 duplication.
// ---------------------------------------------------------------------------
__global__ __launch_bounds__(256) void transpose_w_kernel(
    const float* __restrict__ dw,
    const float* __restrict__ ow,
    const float* __restrict__ mw)
{
    int i = blockIdx.x * 256 + threadIdx.x;
    if (i < 9 * CIN * OO) {
        int o = i & 127, c = (i >> 7) & 127, k = i >> 14;
        g_wt2[i] = dup_host(dw[(o * CIN + c) * 9 + k]);
    }
    if (i < 9 * CIN * 32) {
        int s = i & 31, c = (i >> 5) & 127, k = i >> 12;
        float w = 0.f;
        if (s < 18)      w = ow[(s * CIN + c) * 9 + k];
        else if (s < 27) w = mw[((s - 18) * CIN + c) * 9 + k];
        g_owt2[i] = dup_host(w);
    }
}

// ---------------------------------------------------------------------------
// Kernel 1: offset conv (18ch) + mask conv (9ch, sigmoid), fused implicit GEMM
// Ping-pong: 1 barrier per chunk; weights via cp.async, values via reg prefetch.
// ---------------------------------------------------------------------------
__global__ __launch_bounds__(256, 2) void offmask_kernel(
    const float* __restrict__ x2,
    const float* __restrict__ offset_b, const float* __restrict__ mask_b)
{
    __shared__ __align__(16) ull   wsm2[2][16][32];   // 8KB
    __shared__ __align__(16) float vsm [2][16][64];   // 8KB

    const int tid = threadIdx.x;
    const int b  = blockIdx.y;
    const int p0 = blockIdx.x * PT;
    const int tx = tid & 15;
    const int ty = tid >> 4;

    // value-prefetch lane mapping (4 values per thread)
    const int vcc = tid >> 6;           // base cc for r-loop: cc = vcc + r*4
    const int vpl = tid & 63;
    const int vho = (p0 + vpl) / WWW, vwo = (p0 + vpl) % WWW;
    // weight cp.async mapping: 16 cc x 32 slots = 512 ull = 4KB, 16B per thread
    const int wcc = tid >> 4, wo2 = (tid & 15) * 2;

    ull acc2[2][2] = {{0ull,0ull},{0ull,0ull}};

    // ---- prologue: stage chunk 0 ----
    {
        cp_async16(&wsm2[0][wcc][wo2], &g_owt2[(0 * CIN + 0 + wcc) * 32 + wo2]);
#pragma unroll
        for (int r = 0; r < 4; r++) {
            int cc = vcc + r * 4;   // wrong stride fix below
        }
        // direct stage values for chunk 0 (k=0: ky=0,kx=0)
#pragma unroll
        for (int r = 0; r < 4; r++) {
            int idx = tid + r * 256;
            int cc = idx >> 6, pl = idx & 63;
            int p = p0 + pl;
            int ho = p / WWW, wo = p % WWW;
            int y = ho - 1, x = wo - 1;
            float v = 0.f;
            if ((unsigned)y < (unsigned)HH && (unsigned)x < (unsigned)WWW)
                v = x2[((b * CIN + cc) * HH + y) * WWW + x];
            vsm[0][cc][pl] = v;
        }
        cp_commit(); cp_wait0();
        __syncthreads();
    }

    for (int ch = 0; ch < 72; ch++) {
        const int s = ch & 1;
        const bool hn = ch < 71;
        const int nk = (ch + 1) / 8, ncb = (ch + 1) & 7;
        const int nky = nk / 3, nkx = nk % 3, nc0 = ncb * 16;

        // stage next weights via cp.async
        if (hn) {
            cp_async16(&wsm2[s ^ 1][wcc][wo2], &g_owt2[(nk * CIN + nc0 + wcc) * 32 + wo2]);
            cp_commit();
        }
        // prefetch next values into regs
        float pv[4];
        if (hn) {
#pragma unroll
            for (int r = 0; r < 4; r++) {
                int cc = (tid + r * 256) >> 6;
                int y = vho - 1 + nky, x = vwo - 1 + nkx;
                float v = 0.f;
                if ((unsigned)y < (unsigned)HH && (unsigned)x < (unsigned)WWW)
                    v = x2[((b * CIN + nc0 + cc) * HH + y) * WWW + x];
                pv[r] = v;
            }
        }
        // math on buffer s
#pragma unroll
        for (int cc = 0; cc < 16; cc++) {
            ulonglong2 w = *(const ulonglong2*)&wsm2[s][cc][ty * 2];
            ulonglong2 v = *(const ulonglong2*)&vsm[s][cc][tx * 4];
            fma2(acc2[0][0], w.x, v.x);
            fma2(acc2[0][1], w.x, v.y);
            fma2(acc2[1][0], w.y, v.x);
            fma2(acc2[1][1], w.y, v.y);
        }
        // publish next values
        if (hn) {
#pragma unroll
            for (int r = 0; r < 4; r++) {
                int cc = (tid + r * 256) >> 6;
                vsm[s ^ 1][cc][vpl] = pv[r];
            }
        }
        cp_wait0();
        __syncthreads();
    }

    // epilogue: bias; sigmoid for mask channels
#pragma unroll
    for (int i = 0; i < 2; i++) {
        int oc = ty * 2 + i;
        float a[4];
        float2 lo = unpack2(acc2[i][0]);
        float2 hi = unpack2(acc2[i][1]);
        a[0] = lo.x; a[1] = lo.y; a[2] = hi.x; a[3] = hi.y;
#pragma unroll
        for (int j = 0; j < 4; j++) {
            int p = p0 + tx * 4 + j;
            if (oc < 18) {
                g_off[(b * 18 + oc) * PP + p] = a[j] + offset_b[oc];
            } else if (oc < 27) {
                float sg = a[j] + mask_b[oc - 18];
                g_mask[(b * 9 + (oc - 18)) * PP + p] = 1.f / (1.f + expf(-sg));
            }
        }
    }
}

// ---------------------------------------------------------------------------
// Kernel 2: modulated deformable conv v2 as implicit GEMM, ping-pong pipelined.
//   out[128o, 64p] = W[128, 1152] @ V[1152, 64]
// ---------------------------------------------------------------------------
__global__ __launch_bounds__(256, 2) void deform_kernel(
    const float* __restrict__ x,
    const float* __restrict__ deform_b,
    float* __restrict__ out)
{
    __shared__ __align__(16) int   sidx[9][64][4];     // 9KB
    __shared__ __align__(16) float swt [9][64][4];     // 9KB
    __shared__ __align__(16) ull   wsm2[2][16][128];   // 32KB
    __shared__ __align__(16) float vsm [2][16][64];    // 8KB

    const int tid = threadIdx.x;
    const int b  = blockIdx.y;
    const int p0 = blockIdx.x * PT;
    const int tx = tid & 15;        // -> 4 pixels
    const int ty = tid >> 4;        // -> 8 out channels
    const int vpl = tid & 63;       // value-staging pixel lane

    // weight cp.async mapping: 16 cc x 128 o = 2048 ull = 16KB → 4×16B per thread
    // idx = tid + r*256 → cc = idx>>6, pair o2 = (idx&63)*2
    // ---- precompute bilinear corner metadata for 64 pixels x 9 taps ----
    for (int idx = tid; idx < 9 * 64; idx += 256) {
        int k = idx >> 6, pl = idx & 63;
        int p  = p0 + pl;
        int ho = p / WWW, wo = p % WWW;
        int ky = k / 3, kx = k % 3;
        float dy = g_off[(b * 18 + 2 * k    ) * PP + p];
        float dx = g_off[(b * 18 + 2 * k + 1) * PP + p];
        float m  = g_mask[(b * 9 + k) * PP + p];
        float py = (float)(ho - 1 + ky) + dy;
        float px = (float)(wo - 1 + kx) + dx;
        float fy = floorf(py), fx = floorf(px);
        int y0 = (int)fy, x0 = (int)fx;
        int y1 = y0 + 1,  x1 = x0 + 1;
        float ly = py - fy, lx = px - fx;
        float hy = 1.f - ly, hx = 1.f - lx;
        bool vy0 = (unsigned)y0 < (unsigned)HH, vy1 = (unsigned)y1 < (unsigned)HH;
        bool vx0 = (unsigned)x0 < (unsigned)WWW, vx1 = (unsigned)x1 < (unsigned)WWW;
        bool v00 = vy0 && vx0, v01 = vy0 && vx1, v10 = vy1 && vx0, v11 = vy1 && vx1;
        sidx[k][pl][0] = v00 ? (y0 * WWW + x0) : 0;
        sidx[k][pl][1] = v01 ? (y0 * WWW + x1) : 0;
        sidx[k][pl][2] = v10 ? (y1 * WWW + x0) : 0;
        sidx[k][pl][3] = v11 ? (y1 * WWW + x1) : 0;
        swt[k][pl][0] = v00 ? hy * hx * m : 0.f;
        swt[k][pl][1] = v01 ? hy * lx * m : 0.f;
        swt[k][pl][2] = v10 ? ly * hx * m : 0.f;
        swt[k][pl][3] = v11 ? ly * lx * m : 0.f;
    }
    __syncthreads();

    ull acc2[8][2];
#pragma unroll
    for (int i = 0; i < 8; i++) { acc2[i][0] = 0ull; acc2[i][1] = 0ull; }

    // ---- prologue: stage chunk 0 (k=0, cb=0) ----
    {
        ull* wflat = &wsm2[0][0][0];
#pragma unroll
        for (int r = 0; r < 4; r++) {
            int idx = tid + r * 256;
            cp_async16(&wflat[idx * 2], &g_wt2[idx * 2]);   // k=0,c0=0 → flat
        }
#pragma unroll
        for (int r = 0; r < 4; r++) {
            int idx = tid + r * 256;
            int cc = idx >> 6;
            const float* base = x + (size_t)(b * CIN + cc) * PP;
            int4   id = *(const int4*)  &sidx[0][vpl][0];
            float4 w  = *(const float4*)&swt [0][vpl][0];
            float v = w.x * base[id.x];
            v = fmaf(w.y, base[id.y], v);
            v = fmaf(w.z, base[id.z], v);
            v = fmaf(w.w, base[id.w], v);
            vsm[0][cc][vpl] = v;
        }
        cp_commit(); cp_wait0();
        __syncthreads();
    }

    for (int ch = 0; ch < 72; ch++) {
        const int s = ch & 1;
        const bool hn = ch < 71;
        const int nk = (ch + 1) >> 3, ncb = (ch + 1) & 7;
        const int nc0 = ncb * 16;

        // stage next weights via cp.async
        if (hn) {
            ull* wflat = &wsm2[s ^ 1][0][0];
#pragma unroll
            for (int r = 0; r < 4; r++) {
                int idx = tid + r * 256;
                int cc = idx >> 6, o2 = (idx & 63) * 2;
                cp_async16(&wflat[idx * 2], &g_wt2[(nk * CIN + nc0 + cc) * OO + o2]);
            }
            cp_commit();
        }
        // prefetch next bilinear corners into regs
        float cr[4][4];
        float4 ws[4];
        if (hn) {
#pragma unroll
            for (int r = 0; r < 4; r++) {
                int cc = (tid + r * 256) >> 6;
                const float* base = x + (size_t)(b * CIN + nc0 + cc) * PP;
                int4 id = *(const int4*)&sidx[nk][vpl][0];
                ws[r]   = *(const float4*)&swt[nk][vpl][0];
                cr[r][0] = base[id.x];
                cr[r][1] = base[id.y];
                cr[r][2] = base[id.z];
                cr[r][3] = base[id.w];
            }
        }
        // math on buffer s: 16 rank-1 updates of 8oc x 4p (f32x2)
#pragma unroll
        for (int cc = 0; cc < 16; cc++) {
            ulonglong2 w01 = *(const ulonglong2*)&wsm2[s][cc][ty * 8];
            ulonglong2 w23 = *(const ulonglong2*)&wsm2[s][cc][ty * 8 + 2];
            ulonglong2 w45 = *(const ulonglong2*)&wsm2[s][cc][ty * 8 + 4];
            ulonglong2 w67 = *(const ulonglong2*)&wsm2[s][cc][ty * 8 + 6];
            ulonglong2 v   = *(const ulonglong2*)&vsm [s][cc][tx * 4];
            fma2(acc2[0][0], w01.x, v.x);  fma2(acc2[0][1], w01.x, v.y);
            fma2(acc2[1][0], w01.y, v.x);  fma2(acc2[1][1], w01.y, v.y);
            fma2(acc2[2][0], w23.x, v.x);  fma2(acc2[2][1], w23.x, v.y);
            fma2(acc2[3][0], w23.y, v.x);  fma2(acc2[3][1], w23.y, v.y);
            fma2(acc2[4][0], w45.x, v.x);  fma2(acc2[4][1], w45.x, v.y);
            fma2(acc2[5][0], w45.y, v.x);  fma2(acc2[5][1], w45.y, v.y);
            fma2(acc2[6][0], w67.x, v.x);  fma2(acc2[6][1], w67.x, v.y);
            fma2(acc2[7][0], w67.y, v.x);  fma2(acc2[7][1], w67.y, v.y);
        }
        // combine corners and publish next values
        if (hn) {
#pragma unroll
            for (int r = 0; r < 4; r++) {
                int cc = (tid + r * 256) >> 6;
                float v = ws[r].x * cr[r][0];
                v = fmaf(ws[r].y, cr[r][1], v);
                v = fmaf(ws[r].z, cr[r][2], v);
                v = fmaf(ws[r].w, cr[r][3], v);
                vsm[s ^ 1][cc][vpl] = v;
            }
        }
        cp_wait0();
        __syncthreads();
    }

    // epilogue: bias + vectorized store
#pragma unroll
    for (int i = 0; i < 8; i++) {
        int oc = ty * 8 + i;
        float bias = deform_b[oc];
        float2 lo = unpack2(acc2[i][0]);
        float2 hi = unpack2(acc2[i][1]);
        float4 o;
        o.x = lo.x + bias;
        o.y = lo.y + bias;
        o.z = hi.x + bias;
        o.w = hi.y + bias;
        *(float4*)&out[(size_t)(b * OO + oc) * PP + p0 + tx * 4] = o;
    }
}

// ---------------------------------------------------------------------------
extern "C" void kernel_launch(void* const* d_in, const int* in_sizes, int n_in,
                              void* d_out, int out_size)
{
    const float* x        = (const float*)d_in[0];
    const float* x2       = (const float*)d_in[1];
    const float* offset_w = (const float*)d_in[2];
    const float* offset_b = (const float*)d_in[3];
    const float* mask_w   = (const float*)d_in[4];
    const float* mask_b   = (const float*)d_in[5];
    const float* deform_w = (const float*)d_in[6];
    const float* deform_b = (const float*)d_in[7];
    float* out = (float*)d_out;

    transpose_w_kernel<<<(9 * CIN * OO + 255) / 256, 256>>>(deform_w, offset_w, mask_w);
    dim3 grid(NPT, BB);
    offmask_kernel<<<grid, 256>>>(x2, offset_b, mask_b);
    deform_kernel<<<grid, 256>>>(x, deform_b, out);
}